// round 16
// baseline (speedup 1.0000x reference)
#include <cuda_runtime.h>
#include <math.h>

// Problem constants
#define BB    2
#define NN    2048
#define IND   256
#define DIMV  256
#define HH    8
#define DHH   32
#define ROWS  (BB*NN)          // 4096
#define TEMP  0.17677669529663687f  // fp32(1/sqrt(32))

#define MSG_OFF   0
#define SCORE_OFF 1048576       // ROWS*DIMV
#define IDX_OFF   1179648       // SCORE_OFF + ROWS*4*8

#define NSPLIT 8
#define KEYS_PER_SPLIT 256

// Scratch (static device memory; no allocations allowed)
__device__ float g_xn [ROWS*IND];
__device__ float g_q  [ROWS*DIMV];   // [b][h][s][d]
__device__ float g_kp [16*1024*32*2];// K pair-interleaved: [bh][s/2][d][s&1]
__device__ float g_v  [ROWS*DIMV];   // [b][h][s][d]
__device__ float g_msg[ROWS*DIMV];   // [row][dim]
// split-KV partials: index p = (split*16 + bh)*2048 + q
__device__ float g_pacc[NSPLIT*16*2048*32];
__device__ float g_pz  [NSPLIT*16*2048];
__device__ float g_pt  [NSPLIT*16*2048*4];
__device__ int   g_pi  [NSPLIT*16*2048*4];

typedef unsigned long long ull;

__device__ __forceinline__ ull fma2(ull a, ull b, ull c) {
    ull d; asm("fma.rn.f32x2 %0,%1,%2,%3;" : "=l"(d) : "l"(a), "l"(b), "l"(c)); return d;
}
__device__ __forceinline__ ull pack2(float x) {
    ull d; unsigned u = __float_as_uint(x);
    asm("mov.b64 %0,{%1,%1};" : "=l"(d) : "r"(u)); return d;
}
__device__ __forceinline__ void unpack2(ull a, float& lo, float& hi) {
    unsigned x, y; asm("mov.b64 {%0,%1},%2;" : "=r"(x), "=r"(y) : "l"(a));
    lo = __uint_as_float(x); hi = __uint_as_float(y);
}
__device__ __forceinline__ void cp16(unsigned dst, const void* src) {
    asm volatile("cp.async.cg.shared.global [%0], [%1], 16;" :: "r"(dst), "l"(src));
}
__device__ __forceinline__ void cp_commit() {
    asm volatile("cp.async.commit_group;");
}
__device__ __forceinline__ void cp_wait0() {
    asm volatile("cp.async.wait_group 0;");
}

// ---------------------------------------------------------------------------
// 1) LayerNorm (unchanged — exactness-critical path)
// ---------------------------------------------------------------------------
__global__ void ln_kernel(const float* __restrict__ x,
                          const float* __restrict__ gam,
                          const float* __restrict__ bet) {
    __shared__ float red[8];
    int row = blockIdx.x, tid = threadIdx.x;
    int w = tid >> 5, ln = tid & 31;
    float v = x[row*IND + tid];

    float s = v;
#pragma unroll
    for (int o = 16; o > 0; o >>= 1) s += __shfl_xor_sync(0xffffffffu, s, o);
    if (ln == 0) red[w] = s;
    __syncthreads();
    float S = 0.f;
#pragma unroll
    for (int i = 0; i < 8; i++) S += red[i];
    float mu = S * (1.0f/IND);

    float d  = v - mu;
    float q  = d * d;
    __syncthreads();
#pragma unroll
    for (int o = 16; o > 0; o >>= 1) q += __shfl_xor_sync(0xffffffffu, q, o);
    if (ln == 0) red[w] = q;
    __syncthreads();
    float Q = 0.f;
#pragma unroll
    for (int i = 0; i < 8; i++) Q += red[i];
    float var = Q * (1.0f/IND);

    float denom = __fsqrt_rn(var + 1e-5f);
    float xh    = __fdiv_rn(d, denom);
    g_xn[row*IND + tid] = xh * gam[tid] + bet[tid];
}

// ---------------------------------------------------------------------------
// 2) QKV GEMM (R15 verbatim): 64x128 tile, FFMA2 col pairs, register
//    double-buffered loads. K written pair-interleaved.
// ---------------------------------------------------------------------------
__global__ void __launch_bounds__(256) qkv_gemm(const float* __restrict__ W) {
    __shared__ float As[32][68];
    __shared__ ull   Bs2[32][66];
    int tid = threadIdx.x;
    int r0 = blockIdx.y * 64, n0 = blockIdx.x * 128;
    int tx = tid & 15, ty = tid >> 4;
    float* Bf = (float*)Bs2;

    ull c2[4][4];
#pragma unroll
    for (int i = 0; i < 4; i++)
#pragma unroll
        for (int u = 0; u < 4; u++) c2[i][u] = 0ull;

    int am = tid >> 3,            ak4 = (tid & 7) << 2;
    int am2 = (tid + 256) >> 3,   ak42 = ((tid + 256) & 7) << 2;
    float4 a0r, a1r, b0r, b1r, b2r, b3r;

    a0r = *(const float4*)&g_xn[(r0+am )*256 + ak4 ];
    a1r = *(const float4*)&g_xn[(r0+am2)*256 + ak42];
#pragma unroll
    for (int r = 0; r < 4; r++) {
        int f = tid + 256*r;
        int m = f >> 3, k4 = (f & 7) << 2;
        float4 bv = *(const float4*)&W[(n0+m)*256 + k4];
        if (r == 0) b0r = bv; else if (r == 1) b1r = bv; else if (r == 2) b2r = bv; else b3r = bv;
    }

    for (int k0 = 0; k0 < 256; k0 += 32) {
        As[ak4 +0][am ]=a0r.x; As[ak4 +1][am ]=a0r.y; As[ak4 +2][am ]=a0r.z; As[ak4 +3][am ]=a0r.w;
        As[ak42+0][am2]=a1r.x; As[ak42+1][am2]=a1r.y; As[ak42+2][am2]=a1r.z; As[ak42+3][am2]=a1r.w;
#pragma unroll
        for (int r = 0; r < 4; r++) {
            int f = tid + 256*r;
            int m = f >> 3, k4 = (f & 7) << 2;
            float4 bv = (r == 0) ? b0r : (r == 1) ? b1r : (r == 2) ? b2r : b3r;
            Bf[(k4+0)*132+m]=bv.x; Bf[(k4+1)*132+m]=bv.y;
            Bf[(k4+2)*132+m]=bv.z; Bf[(k4+3)*132+m]=bv.w;
        }
        __syncthreads();

        if (k0 + 32 < 256) {
            int kn = k0 + 32;
            a0r = *(const float4*)&g_xn[(r0+am )*256 + kn + ak4 ];
            a1r = *(const float4*)&g_xn[(r0+am2)*256 + kn + ak42];
#pragma unroll
            for (int r = 0; r < 4; r++) {
                int f = tid + 256*r;
                int m = f >> 3, k4 = (f & 7) << 2;
                float4 bv = *(const float4*)&W[(n0+m)*256 + kn + k4];
                if (r == 0) b0r = bv; else if (r == 1) b1r = bv; else if (r == 2) b2r = bv; else b3r = bv;
            }
        }

#pragma unroll
        for (int kk = 0; kk < 32; kk++) {
            float4 a = *(const float4*)&As[kk][ty*4];
            ull ap0 = pack2(a.x), ap1 = pack2(a.y), ap2 = pack2(a.z), ap3 = pack2(a.w);
#pragma unroll
            for (int u = 0; u < 4; u++) {
                ull b = Bs2[kk][tx + 16*u];
                c2[0][u] = fma2(ap0, b, c2[0][u]);
                c2[1][u] = fma2(ap1, b, c2[1][u]);
                c2[2][u] = fma2(ap2, b, c2[2][u]);
                c2[3][u] = fma2(ap3, b, c2[3][u]);
            }
        }
        __syncthreads();
    }
#pragma unroll
    for (int i = 0; i < 4; i++)
#pragma unroll
        for (int u = 0; u < 4; u++) {
            float lo, hi; unpack2(c2[i][u], lo, hi);
            int row = r0 + ty*4 + i;
            int col = n0 + 2*(tx + 16*u);
            int which = col >> 8, h = (col >> 5) & 7, d = col & 31;
            int b = row >> 11, s = row & 2047;
            int bh = (b<<3) + h;
            if (which == 1) {
                float* kp = g_kp + ((((size_t)bh*1024 + (s>>1))*32 + d) << 1) + (s & 1);
                kp[0] = lo; kp[2] = hi;
            } else {
                float* dst = (which == 0) ? g_q : g_v;
                *(float2*)&dst[((size_t)bh*2048 + s)*32 + d] = make_float2(lo, hi);
            }
        }
}

// ---------------------------------------------------------------------------
// 3) Attention (split-KV x8): 2048 blocks x 128 threads; block = 128 queries
//    x 256 keys for one (b,h,split). R15 inner loop verbatim (two interleaved
//    score chains, single-barrier double buffering). launch_bounds(128,3) —
//    the R10 regression was the (128,4) spill, not the split count.
//    Each f32x2 score lane is a strict sequential ascending-d fp32 chain
//    (bit-identical to scalar).
// ---------------------------------------------------------------------------
#define KT 64
#define NTILE (KEYS_PER_SPLIT/KT)

__global__ void __launch_bounds__(128, 3) attn_kernel() {
    __shared__ ull   Kp[2][KT/2][32];   // 8 KB per stage
    __shared__ float Vs[2][KT][32];     // 8 KB per stage

    int bid   = blockIdx.x;               // 0..2047
    int qg    = bid & 15;
    int bh    = (bid >> 4) & 15;
    int split = bid >> 8;                 // 0..7
    int tid   = threadIdx.x;
    int l     = qg*128 + tid;

    ull qp[32];
    {
        const float4* qrow = (const float4*)(g_q + ((size_t)bh*2048 + l)*32);
#pragma unroll
        for (int c = 0; c < 8; c++) {
            float4 f = qrow[c];
            qp[4*c+0] = pack2(f.x); qp[4*c+1] = pack2(f.y);
            qp[4*c+2] = pack2(f.z); qp[4*c+3] = pack2(f.w);
        }
    }

    ull acc2[16];
#pragma unroll
    for (int i = 0; i < 16; i++) acc2[i] = 0ull;

    float Z = 0.f;
    float t0 = -3.0e38f, t1 = -3.0e38f, t2 = -3.0e38f, t3 = -3.0e38f;
    int   i0 = 0, i1 = 0, i2 = 0, i3 = 0;

    const char* kg = (const char*)g_kp + (size_t)bh*262144 + (size_t)split*KEYS_PER_SPLIT*128;
    const char* vg = (const char*)g_v  + (size_t)bh*262144 + (size_t)split*KEYS_PER_SPLIT*128;

    unsigned kbase0 = (unsigned)__cvta_generic_to_shared(&Kp[0][0][0]);
    unsigned kbase1 = (unsigned)__cvta_generic_to_shared(&Kp[1][0][0]);
    unsigned vbase0 = (unsigned)__cvta_generic_to_shared(&Vs[0][0][0]);
    unsigned vbase1 = (unsigned)__cvta_generic_to_shared(&Vs[1][0][0]);

    // prologue: tile 0 -> stage 0
    {
#pragma unroll
        for (int i = 0; i < 4; i++) {
            int c = tid + i*128;
            cp16(kbase0 + c*16, kg + c*16);
            cp16(vbase0 + c*16, vg + c*16);
        }
        cp_commit();
    }

    for (int t = 0; t < NTILE; t++) {
        int buf = t & 1;
        cp_wait0();
        __syncthreads();
        if (t + 1 < NTILE) {
            unsigned kb2 = (buf ? kbase0 : kbase1);
            unsigned vb2 = (buf ? vbase0 : vbase1);
            const char* ks = kg + (size_t)(t+1)*8192;
            const char* vs = vg + (size_t)(t+1)*8192;
#pragma unroll
            for (int i = 0; i < 4; i++) {
                int c = tid + i*128;
                cp16(kb2 + c*16, ks + c*16);
                cp16(vb2 + c*16, vs + c*16);
            }
            cp_commit();
        }

#pragma unroll 2
        for (int p = 0; p < KT/2; p += 2) {
            const ulonglong2* kr0 = (const ulonglong2*)&Kp[buf][p][0];
            const ulonglong2* kr1 = (const ulonglong2*)&Kp[buf][p+1][0];
            ull s0 = 0ull, s1 = 0ull;
#pragma unroll
            for (int u = 0; u < 16; u++) {
                ulonglong2 k0 = kr0[u], k1 = kr1[u];
                ull qa = qp[2*u], qb = qp[2*u+1];
                s0 = fma2(qa, k0.x, s0);
                s1 = fma2(qa, k1.x, s1);
                s0 = fma2(qb, k0.y, s0);
                s1 = fma2(qb, k1.y, s1);
            }

            // ---- pair 0 (keys 2p, 2p+1) ----
            {
                float sA, sB; unpack2(s0, sA, sB);
                sA *= TEMP; sB *= TEMP;
                float eA = __expf(sA), eB = __expf(sB);
                Z += eA; Z += eB;
                ull eAp = pack2(eA), eBp = pack2(eB);

                const ulonglong2* va  = (const ulonglong2*)&Vs[buf][2*p][0];
                const ulonglong2* vbp = (const ulonglong2*)&Vs[buf][2*p+1][0];
#pragma unroll
                for (int c = 0; c < 8; c++) {
                    ulonglong2 vv = va[c];
                    acc2[2*c]   = fma2(eAp, vv.x, acc2[2*c]);
                    acc2[2*c+1] = fma2(eAp, vv.y, acc2[2*c+1]);
                }
#pragma unroll
                for (int c = 0; c < 8; c++) {
                    ulonglong2 vv = vbp[c];
                    acc2[2*c]   = fma2(eBp, vv.x, acc2[2*c]);
                    acc2[2*c+1] = fma2(eBp, vv.y, acc2[2*c+1]);
                }

                int s = split*KEYS_PER_SPLIT + t*KT + 2*p;
                if (sA > t3) {
                    if (sA > t1) {
                        if (sA > t0) { t3=t2;i3=i2; t2=t1;i2=i1; t1=t0;i1=i0; t0=sA;i0=s; }
                        else         { t3=t2;i3=i2; t2=t1;i2=i1; t1=sA;i1=s; }
                    } else {
                        if (sA > t2) { t3=t2;i3=i2; t2=sA;i2=s; }
                        else         { t3=sA;i3=s; }
                    }
                }
                s++;
                if (sB > t3) {
                    if (sB > t1) {
                        if (sB > t0) { t3=t2;i3=i2; t2=t1;i2=i1; t1=t0;i1=i0; t0=sB;i0=s; }
                        else         { t3=t2;i3=i2; t2=t1;i2=i1; t1=sB;i1=s; }
                    } else {
                        if (sB > t2) { t3=t2;i3=i2; t2=sB;i2=s; }
                        else         { t3=sB;i3=s; }
                    }
                }
            }

            // ---- pair 1 (keys 2p+2, 2p+3) ----
            {
                float sA, sB; unpack2(s1, sA, sB);
                sA *= TEMP; sB *= TEMP;
                float eA = __expf(sA), eB = __expf(sB);
                Z += eA; Z += eB;
                ull eAp = pack2(eA), eBp = pack2(eB);

                const ulonglong2* va  = (const ulonglong2*)&Vs[buf][2*p+2][0];
                const ulonglong2* vbp = (const ulonglong2*)&Vs[buf][2*p+3][0];
#pragma unroll
                for (int c = 0; c < 8; c++) {
                    ulonglong2 vv = va[c];
                    acc2[2*c]   = fma2(eAp, vv.x, acc2[2*c]);
                    acc2[2*c+1] = fma2(eAp, vv.y, acc2[2*c+1]);
                }
#pragma unroll
                for (int c = 0; c < 8; c++) {
                    ulonglong2 vv = vbp[c];
                    acc2[2*c]   = fma2(eBp, vv.x, acc2[2*c]);
                    acc2[2*c+1] = fma2(eBp, vv.y, acc2[2*c+1]);
                }

                int s = split*KEYS_PER_SPLIT + t*KT + 2*p + 2;
                if (sA > t3) {
                    if (sA > t1) {
                        if (sA > t0) { t3=t2;i3=i2; t2=t1;i2=i1; t1=t0;i1=i0; t0=sA;i0=s; }
                        else         { t3=t2;i3=i2; t2=t1;i2=i1; t1=sA;i1=s; }
                    } else {
                        if (sA > t2) { t3=t2;i3=i2; t2=sA;i2=s; }
                        else         { t3=sA;i3=s; }
                    }
                }
                s++;
                if (sB > t3) {
                    if (sB > t1) {
                        if (sB > t0) { t3=t2;i3=i2; t2=t1;i2=i1; t1=t0;i1=i0; t0=sB;i0=s; }
                        else         { t3=t2;i3=i2; t2=t1;i2=i1; t1=sB;i1=s; }
                    } else {
                        if (sB > t2) { t3=t2;i3=i2; t2=sB;i2=s; }
                        else         { t3=sB;i3=s; }
                    }
                }
            }
        }
    }

    // ---- write partials ----
    size_t p = ((size_t)(split*16 + bh))*2048 + l;
    float* pa = g_pacc + p*32;
#pragma unroll
    for (int i = 0; i < 16; i++) {
        float lo, hi; unpack2(acc2[i], lo, hi);
        *(float2*)&pa[2*i] = make_float2(lo, hi);
    }
    g_pz[p] = Z;
    g_pt[p*4+0] = t0; g_pt[p*4+1] = t1; g_pt[p*4+2] = t2; g_pt[p*4+3] = t3;
    g_pi[p*4+0] = i0; g_pi[p*4+1] = i1; g_pi[p*4+2] = i2; g_pi[p*4+3] = i3;
}

// ---------------------------------------------------------------------------
// 3b) Merge: 4 threads per (bh,q), each owns 8 dims. Exact 8-way top-4 merge
//     via shift-down sorted heads; ascending-split strict > scan keeps
//     earliest split on ties = lowest key index = JAX tie rule.
// ---------------------------------------------------------------------------
__global__ void __launch_bounds__(128) attn_merge(float* __restrict__ out) {
    int idx = blockIdx.x * 128 + threadIdx.x;     // 0..131071
    int quarter = idx & 3;                        // 8 dims
    int q   = (idx >> 2) & 2047;
    int bh  = idx >> 13;
    int b   = bh >> 3, h = bh & 7;

    float  T[NSPLIT][4];
    int    I[NSPLIT][4];
    float  Z = 0.f;
#pragma unroll
    for (int s = 0; s < NSPLIT; s++) {
        size_t ps = (size_t)(s*16 + bh)*2048 + q;
#pragma unroll
        for (int r = 0; r < 4; r++) {
            T[s][r] = g_pt[ps*4+r];
            I[s][r] = g_pi[ps*4+r];
        }
        Z += g_pz[ps];
    }

    float ts[4]; int is[4];
#pragma unroll
    for (int r = 0; r < 4; r++) {
        float best = -3.3e38f; int bs = 0;
#pragma unroll
        for (int s = 0; s < NSPLIT; s++)
            if (T[s][0] > best) { best = T[s][0]; bs = s; }
        ts[r] = best;
#pragma unroll
        for (int s = 0; s < NSPLIT; s++)
            if (bs == s) {
                is[r] = I[s][0];
                T[s][0]=T[s][1]; T[s][1]=T[s][2]; T[s][2]=T[s][3]; T[s][3]=-3.3e38f;
                I[s][0]=I[s][1]; I[s][1]=I[s][2]; I[s][2]=I[s][3];
            }
    }

    float e0 = __expf(ts[0]), e1 = __expf(ts[1]), e2v = __expf(ts[2]), e3 = __expf(ts[3]);
    int dbase = quarter * 8;   // 8 dims = 2 float4
    const float* v0 = g_v + ((size_t)bh*2048 + is[0])*32 + dbase;
    const float* v1 = g_v + ((size_t)bh*2048 + is[1])*32 + dbase;
    const float* v2 = g_v + ((size_t)bh*2048 + is[2])*32 + dbase;
    const float* v3 = g_v + ((size_t)bh*2048 + is[3])*32 + dbase;
    float rZ = 1.0f / Z;

    int rowi = b*2048 + q;
    float* mo = g_msg + (size_t)rowi*256 + h*32 + dbase;
#pragma unroll
    for (int c = 0; c < 2; c++) {
        float sx = 0.f, sy = 0.f, sz = 0.f, sw = 0.f;
#pragma unroll
        for (int s = 0; s < NSPLIT; s++) {
            size_t ps = (size_t)(s*16 + bh)*2048 + q;
            float4 x = *(const float4*)&g_pacc[ps*32 + dbase + 4*c];
            sx += x.x; sy += x.y; sz += x.z; sw += x.w;
        }
        float4 w0 = *(const float4*)&v0[4*c];
        float4 w1 = *(const float4*)&v1[4*c];
        float4 w2 = *(const float4*)&v2[4*c];
        float4 w3 = *(const float4*)&v3[4*c];
        float4 o;
        o.x = (sx - (e0*w0.x + e1*w1.x + e2v*w2.x + e3*w3.x)) * rZ;
        o.y = (sy - (e0*w0.y + e1*w1.y + e2v*w2.y + e3*w3.y)) * rZ;
        o.z = (sz - (e0*w0.z + e1*w1.z + e2v*w2.z + e3*w3.z)) * rZ;
        o.w = (sw - (e0*w0.w + e1*w1.w + e2v*w2.w + e3*w3.w)) * rZ;
        ((float4*)mo)[c] = o;
    }

    if (quarter == 0) {
        float* so = out + SCORE_OFF + rowi*32 + h;
        so[0]  = e0*rZ;  so[8]  = e1*rZ;  so[16] = e2v*rZ; so[24] = e3*rZ;
        float* io = out + IDX_OFF + rowi*32 + h;
        io[0]  = (float)is[0]; io[8]  = (float)is[1];
        io[16] = (float)is[2]; io[24] = (float)is[3];
    }
}

// ---------------------------------------------------------------------------
// 4) Proj GEMM + bias + residual (R15 verbatim): 64x64 tile, 256 thr.
// ---------------------------------------------------------------------------
__global__ void __launch_bounds__(256) proj_gemm(const float* __restrict__ Wp,
                                                 const float* __restrict__ bp,
                                                 float* __restrict__ out) {
    __shared__ float As[32][68];
    __shared__ ull   Bs2[32][34];
    int tid = threadIdx.x;
    int r0 = blockIdx.y * 64, n0 = blockIdx.x * 64;
    int tx = tid & 15, ty = tid >> 4;
    float* Bf = (float*)Bs2;

    ull c2[4][2];
#pragma unroll
    for (int i = 0; i < 4; i++) { c2[i][0] = 0ull; c2[i][1] = 0ull; }

    int am = tid >> 3,          ak4 = (tid & 7) << 2;
    int am2 = (tid + 256) >> 3, ak42 = ((tid + 256) & 7) << 2;
    int bm = tid >> 2,          bk8 = (tid & 3) << 3;
    float4 a0r, a1r, b1r, b2r;

    a0r = *(const float4*)&g_msg[(r0+am )*256 + ak4 ];
    a1r = *(const float4*)&g_msg[(r0+am2)*256 + ak42];
    b1r = *(const float4*)&Wp[(n0+bm)*256 + bk8];
    b2r = *(const float4*)&Wp[(n0+bm)*256 + bk8 + 4];

    for (int k0 = 0; k0 < 256; k0 += 32) {
        As[ak4 +0][am ]=a0r.x; As[ak4 +1][am ]=a0r.y; As[ak4 +2][am ]=a0r.z; As[ak4 +3][am ]=a0r.w;
        As[ak42+0][am2]=a1r.x; As[ak42+1][am2]=a1r.y; As[ak42+2][am2]=a1r.z; As[ak42+3][am2]=a1r.w;
        Bf[(bk8+0)*68+bm]=b1r.x; Bf[(bk8+1)*68+bm]=b1r.y;
        Bf[(bk8+2)*68+bm]=b1r.z; Bf[(bk8+3)*68+bm]=b1r.w;
        Bf[(bk8+4)*68+bm]=b2r.x; Bf[(bk8+5)*68+bm]=b2r.y;
        Bf[(bk8+6)*68+bm]=b2r.z; Bf[(bk8+7)*68+bm]=b2r.w;
        __syncthreads();

        if (k0 + 32 < 256) {
            int kn = k0 + 32;
            a0r = *(const float4*)&g_msg[(r0+am )*256 + kn + ak4 ];
            a1r = *(const float4*)&g_msg[(r0+am2)*256 + kn + ak42];
            b1r = *(const float4*)&Wp[(n0+bm)*256 + kn + bk8];
            b2r = *(const float4*)&Wp[(n0+bm)*256 + kn + bk8 + 4];
        }

#pragma unroll
        for (int kk = 0; kk < 32; kk++) {
            float4 a = *(const float4*)&As[kk][ty*4];
            ull ap0 = pack2(a.x), ap1 = pack2(a.y), ap2 = pack2(a.z), ap3 = pack2(a.w);
#pragma unroll
            for (int u = 0; u < 2; u++) {
                ull b = Bs2[kk][tx + 16*u];
                c2[0][u] = fma2(ap0, b, c2[0][u]);
                c2[1][u] = fma2(ap1, b, c2[1][u]);
                c2[2][u] = fma2(ap2, b, c2[2][u]);
                c2[3][u] = fma2(ap3, b, c2[3][u]);
            }
        }
        __syncthreads();
    }
#pragma unroll
    for (int i = 0; i < 4; i++)
#pragma unroll
        for (int u = 0; u < 2; u++) {
            float lo, hi; unpack2(c2[i][u], lo, hi);
            int row = r0 + ty*4 + i;
            int col = n0 + 2*(tx + 16*u);
            int b = row >> 11, l = row & 2047, h = col >> 5, d = col & 31;
            const float* vres = &g_v[(((b<<3)+h)*2048 + l)*32 + d];
            float2 o;
            o.x = lo + bp[col]   + vres[0];
            o.y = hi + bp[col+1] + vres[1];
            *(float2*)&out[row*256 + col] = o;
        }
}

// ---------------------------------------------------------------------------
extern "C" void kernel_launch(void* const* d_in, const int* in_sizes, int n_in,
                              void* d_out, int out_size) {
    const float* points = (const float*)d_in[0];
    const float* gam    = (const float*)d_in[1];
    const float* bet    = (const float*)d_in[2];
    const float* wqkv   = (const float*)d_in[3];
    const float* wproj  = (const float*)d_in[4];
    const float* bproj  = (const float*)d_in[5];
    float* out = (float*)d_out;

    ln_kernel<<<ROWS, 256>>>(points, gam, bet);
    qkv_gemm <<<dim3(6, 64), 256>>>(wqkv);
    attn_kernel<<<2048, 128>>>();
    attn_merge<<<1024, 128>>>(out);
    proj_gemm<<<dim3(4, 64), 256>>>(wproj, bproj, out);
}

// round 17
// speedup vs baseline: 1.0235x; 1.0235x over previous
#include <cuda_runtime.h>
#include <math.h>

// Problem constants
#define BB    2
#define NN    2048
#define IND   256
#define DIMV  256
#define HH    8
#define DHH   32
#define ROWS  (BB*NN)          // 4096
#define TEMP  0.17677669529663687f  // fp32(1/sqrt(32))

#define MSG_OFF   0
#define SCORE_OFF 1048576       // ROWS*DIMV
#define IDX_OFF   1179648       // SCORE_OFF + ROWS*4*8

#define NSPLIT 4
#define KEYS_PER_SPLIT 512

// Scratch (static device memory; no allocations allowed)
__device__ float g_xn [ROWS*IND];
__device__ float g_q  [ROWS*DIMV];   // [b][h][s][d]
__device__ float g_kp [16*1024*32*2];// K pair-interleaved: [bh][s/2][d][s&1]
__device__ float g_v  [ROWS*DIMV];   // [b][h][s][d]
__device__ float g_msg[ROWS*DIMV];   // [row][dim]
// split-KV partials: index p = (split*16 + bh)*2048 + q
__device__ float g_pacc[NSPLIT*16*2048*32];
__device__ float g_pz  [NSPLIT*16*2048];
__device__ float g_pt  [NSPLIT*16*2048*4];
__device__ int   g_pi  [NSPLIT*16*2048*4];

typedef unsigned long long ull;

__device__ __forceinline__ ull fma2(ull a, ull b, ull c) {
    ull d; asm("fma.rn.f32x2 %0,%1,%2,%3;" : "=l"(d) : "l"(a), "l"(b), "l"(c)); return d;
}
__device__ __forceinline__ ull pack2(float x) {
    ull d; unsigned u = __float_as_uint(x);
    asm("mov.b64 %0,{%1,%1};" : "=l"(d) : "r"(u)); return d;
}
__device__ __forceinline__ void unpack2(ull a, float& lo, float& hi) {
    unsigned x, y; asm("mov.b64 {%0,%1},%2;" : "=r"(x), "=r"(y) : "l"(a));
    lo = __uint_as_float(x); hi = __uint_as_float(y);
}
__device__ __forceinline__ void cp16(unsigned dst, const void* src) {
    asm volatile("cp.async.cg.shared.global [%0], [%1], 16;" :: "r"(dst), "l"(src));
}
__device__ __forceinline__ void cp_commit() {
    asm volatile("cp.async.commit_group;");
}
__device__ __forceinline__ void cp_wait0() {
    asm volatile("cp.async.wait_group 0;");
}

// ---------------------------------------------------------------------------
// 1) LayerNorm (unchanged — exactness-critical path)
// ---------------------------------------------------------------------------
__global__ void ln_kernel(const float* __restrict__ x,
                          const float* __restrict__ gam,
                          const float* __restrict__ bet) {
    __shared__ float red[8];
    int row = blockIdx.x, tid = threadIdx.x;
    int w = tid >> 5, ln = tid & 31;
    float v = x[row*IND + tid];

    float s = v;
#pragma unroll
    for (int o = 16; o > 0; o >>= 1) s += __shfl_xor_sync(0xffffffffu, s, o);
    if (ln == 0) red[w] = s;
    __syncthreads();
    float S = 0.f;
#pragma unroll
    for (int i = 0; i < 8; i++) S += red[i];
    float mu = S * (1.0f/IND);

    float d  = v - mu;
    float q  = d * d;
    __syncthreads();
#pragma unroll
    for (int o = 16; o > 0; o >>= 1) q += __shfl_xor_sync(0xffffffffu, q, o);
    if (ln == 0) red[w] = q;
    __syncthreads();
    float Q = 0.f;
#pragma unroll
    for (int i = 0; i < 8; i++) Q += red[i];
    float var = Q * (1.0f/IND);

    float denom = __fsqrt_rn(var + 1e-5f);
    float xh    = __fdiv_rn(d, denom);
    g_xn[row*IND + tid] = xh * gam[tid] + bet[tid];
}

// ---------------------------------------------------------------------------
// 2) QKV GEMM (R15 verbatim): 64x128 tile, FFMA2 col pairs, register
//    double-buffered loads. K written pair-interleaved.
// ---------------------------------------------------------------------------
__global__ void __launch_bounds__(256) qkv_gemm(const float* __restrict__ W) {
    __shared__ float As[32][68];
    __shared__ ull   Bs2[32][66];
    int tid = threadIdx.x;
    int r0 = blockIdx.y * 64, n0 = blockIdx.x * 128;
    int tx = tid & 15, ty = tid >> 4;
    float* Bf = (float*)Bs2;

    ull c2[4][4];
#pragma unroll
    for (int i = 0; i < 4; i++)
#pragma unroll
        for (int u = 0; u < 4; u++) c2[i][u] = 0ull;

    int am = tid >> 3,            ak4 = (tid & 7) << 2;
    int am2 = (tid + 256) >> 3,   ak42 = ((tid + 256) & 7) << 2;
    float4 a0r, a1r, b0r, b1r, b2r, b3r;

    a0r = *(const float4*)&g_xn[(r0+am )*256 + ak4 ];
    a1r = *(const float4*)&g_xn[(r0+am2)*256 + ak42];
#pragma unroll
    for (int r = 0; r < 4; r++) {
        int f = tid + 256*r;
        int m = f >> 3, k4 = (f & 7) << 2;
        float4 bv = *(const float4*)&W[(n0+m)*256 + k4];
        if (r == 0) b0r = bv; else if (r == 1) b1r = bv; else if (r == 2) b2r = bv; else b3r = bv;
    }

    for (int k0 = 0; k0 < 256; k0 += 32) {
        As[ak4 +0][am ]=a0r.x; As[ak4 +1][am ]=a0r.y; As[ak4 +2][am ]=a0r.z; As[ak4 +3][am ]=a0r.w;
        As[ak42+0][am2]=a1r.x; As[ak42+1][am2]=a1r.y; As[ak42+2][am2]=a1r.z; As[ak42+3][am2]=a1r.w;
#pragma unroll
        for (int r = 0; r < 4; r++) {
            int f = tid + 256*r;
            int m = f >> 3, k4 = (f & 7) << 2;
            float4 bv = (r == 0) ? b0r : (r == 1) ? b1r : (r == 2) ? b2r : b3r;
            Bf[(k4+0)*132+m]=bv.x; Bf[(k4+1)*132+m]=bv.y;
            Bf[(k4+2)*132+m]=bv.z; Bf[(k4+3)*132+m]=bv.w;
        }
        __syncthreads();

        if (k0 + 32 < 256) {
            int kn = k0 + 32;
            a0r = *(const float4*)&g_xn[(r0+am )*256 + kn + ak4 ];
            a1r = *(const float4*)&g_xn[(r0+am2)*256 + kn + ak42];
#pragma unroll
            for (int r = 0; r < 4; r++) {
                int f = tid + 256*r;
                int m = f >> 3, k4 = (f & 7) << 2;
                float4 bv = *(const float4*)&W[(n0+m)*256 + kn + k4];
                if (r == 0) b0r = bv; else if (r == 1) b1r = bv; else if (r == 2) b2r = bv; else b3r = bv;
            }
        }

#pragma unroll
        for (int kk = 0; kk < 32; kk++) {
            float4 a = *(const float4*)&As[kk][ty*4];
            ull ap0 = pack2(a.x), ap1 = pack2(a.y), ap2 = pack2(a.z), ap3 = pack2(a.w);
#pragma unroll
            for (int u = 0; u < 4; u++) {
                ull b = Bs2[kk][tx + 16*u];
                c2[0][u] = fma2(ap0, b, c2[0][u]);
                c2[1][u] = fma2(ap1, b, c2[1][u]);
                c2[2][u] = fma2(ap2, b, c2[2][u]);
                c2[3][u] = fma2(ap3, b, c2[3][u]);
            }
        }
        __syncthreads();
    }
#pragma unroll
    for (int i = 0; i < 4; i++)
#pragma unroll
        for (int u = 0; u < 4; u++) {
            float lo, hi; unpack2(c2[i][u], lo, hi);
            int row = r0 + ty*4 + i;
            int col = n0 + 2*(tx + 16*u);
            int which = col >> 8, h = (col >> 5) & 7, d = col & 31;
            int b = row >> 11, s = row & 2047;
            int bh = (b<<3) + h;
            if (which == 1) {
                float* kp = g_kp + ((((size_t)bh*1024 + (s>>1))*32 + d) << 1) + (s & 1);
                kp[0] = lo; kp[2] = hi;
            } else {
                float* dst = (which == 0) ? g_q : g_v;
                *(float2*)&dst[((size_t)bh*2048 + s)*32 + d] = make_float2(lo, hi);
            }
        }
}

// ---------------------------------------------------------------------------
// 3) Attention (R15 verbatim): split-KV x4, 1024 blocks x 128 threads; two
//    interleaved score chains, single-barrier double buffering. Each f32x2
//    score lane is a strict sequential ascending-d fp32 chain (bit-identical
//    to scalar).
// ---------------------------------------------------------------------------
#define KT 64
#define NTILE (KEYS_PER_SPLIT/KT)

__global__ void __launch_bounds__(128, 3) attn_kernel() {
    __shared__ ull   Kp[2][KT/2][32];   // 8 KB per stage
    __shared__ float Vs[2][KT][32];     // 8 KB per stage

    int bid   = blockIdx.x;               // 0..1023
    int qg    = bid & 15;
    int bh    = (bid >> 4) & 15;
    int split = bid >> 8;                 // 0..3
    int tid   = threadIdx.x;
    int l     = qg*128 + tid;

    ull qp[32];
    {
        const float4* qrow = (const float4*)(g_q + ((size_t)bh*2048 + l)*32);
#pragma unroll
        for (int c = 0; c < 8; c++) {
            float4 f = qrow[c];
            qp[4*c+0] = pack2(f.x); qp[4*c+1] = pack2(f.y);
            qp[4*c+2] = pack2(f.z); qp[4*c+3] = pack2(f.w);
        }
    }

    ull acc2[16];
#pragma unroll
    for (int i = 0; i < 16; i++) acc2[i] = 0ull;

    float Z = 0.f;
    float t0 = -3.0e38f, t1 = -3.0e38f, t2 = -3.0e38f, t3 = -3.0e38f;
    int   i0 = 0, i1 = 0, i2 = 0, i3 = 0;

    const char* kg = (const char*)g_kp + (size_t)bh*262144 + (size_t)split*KEYS_PER_SPLIT*128;
    const char* vg = (const char*)g_v  + (size_t)bh*262144 + (size_t)split*KEYS_PER_SPLIT*128;

    unsigned kbase0 = (unsigned)__cvta_generic_to_shared(&Kp[0][0][0]);
    unsigned kbase1 = (unsigned)__cvta_generic_to_shared(&Kp[1][0][0]);
    unsigned vbase0 = (unsigned)__cvta_generic_to_shared(&Vs[0][0][0]);
    unsigned vbase1 = (unsigned)__cvta_generic_to_shared(&Vs[1][0][0]);

    // prologue: tile 0 -> stage 0
    {
#pragma unroll
        for (int i = 0; i < 4; i++) {
            int c = tid + i*128;
            cp16(kbase0 + c*16, kg + c*16);
            cp16(vbase0 + c*16, vg + c*16);
        }
        cp_commit();
    }

    for (int t = 0; t < NTILE; t++) {
        int buf = t & 1;
        cp_wait0();
        __syncthreads();
        if (t + 1 < NTILE) {
            unsigned kb2 = (buf ? kbase0 : kbase1);
            unsigned vb2 = (buf ? vbase0 : vbase1);
            const char* ks = kg + (size_t)(t+1)*8192;
            const char* vs = vg + (size_t)(t+1)*8192;
#pragma unroll
            for (int i = 0; i < 4; i++) {
                int c = tid + i*128;
                cp16(kb2 + c*16, ks + c*16);
                cp16(vb2 + c*16, vs + c*16);
            }
            cp_commit();
        }

#pragma unroll 2
        for (int p = 0; p < KT/2; p += 2) {
            const ulonglong2* kr0 = (const ulonglong2*)&Kp[buf][p][0];
            const ulonglong2* kr1 = (const ulonglong2*)&Kp[buf][p+1][0];
            ull s0 = 0ull, s1 = 0ull;
#pragma unroll
            for (int u = 0; u < 16; u++) {
                ulonglong2 k0 = kr0[u], k1 = kr1[u];
                ull qa = qp[2*u], qb = qp[2*u+1];
                s0 = fma2(qa, k0.x, s0);
                s1 = fma2(qa, k1.x, s1);
                s0 = fma2(qb, k0.y, s0);
                s1 = fma2(qb, k1.y, s1);
            }

            // ---- pair 0 (keys 2p, 2p+1) ----
            {
                float sA, sB; unpack2(s0, sA, sB);
                sA *= TEMP; sB *= TEMP;
                float eA = __expf(sA), eB = __expf(sB);
                Z += eA; Z += eB;
                ull eAp = pack2(eA), eBp = pack2(eB);

                const ulonglong2* va  = (const ulonglong2*)&Vs[buf][2*p][0];
                const ulonglong2* vbp = (const ulonglong2*)&Vs[buf][2*p+1][0];
#pragma unroll
                for (int c = 0; c < 8; c++) {
                    ulonglong2 vv = va[c];
                    acc2[2*c]   = fma2(eAp, vv.x, acc2[2*c]);
                    acc2[2*c+1] = fma2(eAp, vv.y, acc2[2*c+1]);
                }
#pragma unroll
                for (int c = 0; c < 8; c++) {
                    ulonglong2 vv = vbp[c];
                    acc2[2*c]   = fma2(eBp, vv.x, acc2[2*c]);
                    acc2[2*c+1] = fma2(eBp, vv.y, acc2[2*c+1]);
                }

                int s = split*KEYS_PER_SPLIT + t*KT + 2*p;
                if (sA > t3) {
                    if (sA > t1) {
                        if (sA > t0) { t3=t2;i3=i2; t2=t1;i2=i1; t1=t0;i1=i0; t0=sA;i0=s; }
                        else         { t3=t2;i3=i2; t2=t1;i2=i1; t1=sA;i1=s; }
                    } else {
                        if (sA > t2) { t3=t2;i3=i2; t2=sA;i2=s; }
                        else         { t3=sA;i3=s; }
                    }
                }
                s++;
                if (sB > t3) {
                    if (sB > t1) {
                        if (sB > t0) { t3=t2;i3=i2; t2=t1;i2=i1; t1=t0;i1=i0; t0=sB;i0=s; }
                        else         { t3=t2;i3=i2; t2=t1;i2=i1; t1=sB;i1=s; }
                    } else {
                        if (sB > t2) { t3=t2;i3=i2; t2=sB;i2=s; }
                        else         { t3=sB;i3=s; }
                    }
                }
            }

            // ---- pair 1 (keys 2p+2, 2p+3) ----
            {
                float sA, sB; unpack2(s1, sA, sB);
                sA *= TEMP; sB *= TEMP;
                float eA = __expf(sA), eB = __expf(sB);
                Z += eA; Z += eB;
                ull eAp = pack2(eA), eBp = pack2(eB);

                const ulonglong2* va  = (const ulonglong2*)&Vs[buf][2*p+2][0];
                const ulonglong2* vbp = (const ulonglong2*)&Vs[buf][2*p+3][0];
#pragma unroll
                for (int c = 0; c < 8; c++) {
                    ulonglong2 vv = va[c];
                    acc2[2*c]   = fma2(eAp, vv.x, acc2[2*c]);
                    acc2[2*c+1] = fma2(eAp, vv.y, acc2[2*c+1]);
                }
#pragma unroll
                for (int c = 0; c < 8; c++) {
                    ulonglong2 vv = vbp[c];
                    acc2[2*c]   = fma2(eBp, vv.x, acc2[2*c]);
                    acc2[2*c+1] = fma2(eBp, vv.y, acc2[2*c+1]);
                }

                int s = split*KEYS_PER_SPLIT + t*KT + 2*p + 2;
                if (sA > t3) {
                    if (sA > t1) {
                        if (sA > t0) { t3=t2;i3=i2; t2=t1;i2=i1; t1=t0;i1=i0; t0=sA;i0=s; }
                        else         { t3=t2;i3=i2; t2=t1;i2=i1; t1=sA;i1=s; }
                    } else {
                        if (sA > t2) { t3=t2;i3=i2; t2=sA;i2=s; }
                        else         { t3=sA;i3=s; }
                    }
                }
                s++;
                if (sB > t3) {
                    if (sB > t1) {
                        if (sB > t0) { t3=t2;i3=i2; t2=t1;i2=i1; t1=t0;i1=i0; t0=sB;i0=s; }
                        else         { t3=t2;i3=i2; t2=t1;i2=i1; t1=sB;i1=s; }
                    } else {
                        if (sB > t2) { t3=t2;i3=i2; t2=sB;i2=s; }
                        else         { t3=sB;i3=s; }
                    }
                }
            }
        }
    }

    // ---- write partials ----
    size_t p = ((size_t)(split*16 + bh))*2048 + l;
    float* pa = g_pacc + p*32;
#pragma unroll
    for (int i = 0; i < 16; i++) {
        float lo, hi; unpack2(acc2[i], lo, hi);
        *(float2*)&pa[2*i] = make_float2(lo, hi);
    }
    g_pz[p] = Z;
    g_pt[p*4+0] = t0; g_pt[p*4+1] = t1; g_pt[p*4+2] = t2; g_pt[p*4+3] = t3;
    g_pi[p*4+0] = i0; g_pi[p*4+1] = i1; g_pi[p*4+2] = i2; g_pi[p*4+3] = i3;
}

// ---------------------------------------------------------------------------
// 3b) Merge: 512 blocks x 256 threads (same thread->work map as R15's
//     1024x128; fatter blocks for more resident warps/SM). 4 threads per
//     (bh,q), each owns 8 dims. Exact 4-way top-4 merge; ascending-split
//     strict > keeps JAX tie rule.
// ---------------------------------------------------------------------------
__global__ void __launch_bounds__(256) attn_merge(float* __restrict__ out) {
    int idx = blockIdx.x * 256 + threadIdx.x;     // 0..131071
    int quarter = idx & 3;                        // 8 dims
    int q   = (idx >> 2) & 2047;
    int bh  = idx >> 13;
    int b   = bh >> 3, h = bh & 7;

    size_t pp[NSPLIT];
    float  T[NSPLIT][4];
    int    I[NSPLIT][4];
    float  Z = 0.f;
#pragma unroll
    for (int s = 0; s < NSPLIT; s++) {
        pp[s] = (size_t)(s*16 + bh)*2048 + q;
#pragma unroll
        for (int r = 0; r < 4; r++) {
            T[s][r] = g_pt[pp[s]*4+r];
            I[s][r] = g_pi[pp[s]*4+r];
        }
        Z += g_pz[pp[s]];
    }

    float ts[4]; int is[4];
    int ptr0 = 0, ptr1 = 0, ptr2 = 0, ptr3 = 0;
#pragma unroll
    for (int r = 0; r < 4; r++) {
        float best = -3.3e38f; int bs = 0;
        if (ptr0 < 4 && T[0][ptr0] > best) { best = T[0][ptr0]; bs = 0; }
        if (ptr1 < 4 && T[1][ptr1] > best) { best = T[1][ptr1]; bs = 1; }
        if (ptr2 < 4 && T[2][ptr2] > best) { best = T[2][ptr2]; bs = 2; }
        if (ptr3 < 4 && T[3][ptr3] > best) { best = T[3][ptr3]; bs = 3; }
        ts[r] = best;
        if      (bs == 0) { is[r] = I[0][ptr0]; ptr0++; }
        else if (bs == 1) { is[r] = I[1][ptr1]; ptr1++; }
        else if (bs == 2) { is[r] = I[2][ptr2]; ptr2++; }
        else              { is[r] = I[3][ptr3]; ptr3++; }
    }

    float e0 = __expf(ts[0]), e1 = __expf(ts[1]), e2v = __expf(ts[2]), e3 = __expf(ts[3]);
    int dbase = quarter * 8;   // 8 dims = 2 float4
    const float* v0 = g_v + ((size_t)bh*2048 + is[0])*32 + dbase;
    const float* v1 = g_v + ((size_t)bh*2048 + is[1])*32 + dbase;
    const float* v2 = g_v + ((size_t)bh*2048 + is[2])*32 + dbase;
    const float* v3 = g_v + ((size_t)bh*2048 + is[3])*32 + dbase;
    const float* a0 = g_pacc + pp[0]*32 + dbase;
    const float* a1 = g_pacc + pp[1]*32 + dbase;
    const float* a2 = g_pacc + pp[2]*32 + dbase;
    const float* a3 = g_pacc + pp[3]*32 + dbase;
    float rZ = 1.0f / Z;

    int rowi = b*2048 + q;
    float* mo = g_msg + (size_t)rowi*256 + h*32 + dbase;
#pragma unroll
    for (int c = 0; c < 2; c++) {
        float4 x0 = *(const float4*)&a0[4*c];
        float4 x1 = *(const float4*)&a1[4*c];
        float4 x2 = *(const float4*)&a2[4*c];
        float4 x3 = *(const float4*)&a3[4*c];
        float4 w0 = *(const float4*)&v0[4*c];
        float4 w1 = *(const float4*)&v1[4*c];
        float4 w2 = *(const float4*)&v2[4*c];
        float4 w3 = *(const float4*)&v3[4*c];
        float4 o;
        o.x = ((((x0.x + x1.x) + x2.x) + x3.x) - (e0*w0.x + e1*w1.x + e2v*w2.x + e3*w3.x)) * rZ;
        o.y = ((((x0.y + x1.y) + x2.y) + x3.y) - (e0*w0.y + e1*w1.y + e2v*w2.y + e3*w3.y)) * rZ;
        o.z = ((((x0.z + x1.z) + x2.z) + x3.z) - (e0*w0.z + e1*w1.z + e2v*w2.z + e3*w3.z)) * rZ;
        o.w = ((((x0.w + x1.w) + x2.w) + x3.w) - (e0*w0.w + e1*w1.w + e2v*w2.w + e3*w3.w)) * rZ;
        ((float4*)mo)[c] = o;
    }

    if (quarter == 0) {
        float* so = out + SCORE_OFF + rowi*32 + h;
        so[0]  = e0*rZ;  so[8]  = e1*rZ;  so[16] = e2v*rZ; so[24] = e3*rZ;
        float* io = out + IDX_OFF + rowi*32 + h;
        io[0]  = (float)is[0]; io[8]  = (float)is[1];
        io[16] = (float)is[2]; io[24] = (float)is[3];
    }
}

// ---------------------------------------------------------------------------
// 4) Proj GEMM + bias + residual (R15 verbatim): 64x64 tile, 256 thr.
// ---------------------------------------------------------------------------
__global__ void __launch_bounds__(256) proj_gemm(const float* __restrict__ Wp,
                                                 const float* __restrict__ bp,
                                                 float* __restrict__ out) {
    __shared__ float As[32][68];
    __shared__ ull   Bs2[32][34];
    int tid = threadIdx.x;
    int r0 = blockIdx.y * 64, n0 = blockIdx.x * 64;
    int tx = tid & 15, ty = tid >> 4;
    float* Bf = (float*)Bs2;

    ull c2[4][2];
#pragma unroll
    for (int i = 0; i < 4; i++) { c2[i][0] = 0ull; c2[i][1] = 0ull; }

    int am = tid >> 3,          ak4 = (tid & 7) << 2;
    int am2 = (tid + 256) >> 3, ak42 = ((tid + 256) & 7) << 2;
    int bm = tid >> 2,          bk8 = (tid & 3) << 3;
    float4 a0r, a1r, b1r, b2r;

    a0r = *(const float4*)&g_msg[(r0+am )*256 + ak4 ];
    a1r = *(const float4*)&g_msg[(r0+am2)*256 + ak42];
    b1r = *(const float4*)&Wp[(n0+bm)*256 + bk8];
    b2r = *(const float4*)&Wp[(n0+bm)*256 + bk8 + 4];

    for (int k0 = 0; k0 < 256; k0 += 32) {
        As[ak4 +0][am ]=a0r.x; As[ak4 +1][am ]=a0r.y; As[ak4 +2][am ]=a0r.z; As[ak4 +3][am ]=a0r.w;
        As[ak42+0][am2]=a1r.x; As[ak42+1][am2]=a1r.y; As[ak42+2][am2]=a1r.z; As[ak42+3][am2]=a1r.w;
        Bf[(bk8+0)*68+bm]=b1r.x; Bf[(bk8+1)*68+bm]=b1r.y;
        Bf[(bk8+2)*68+bm]=b1r.z; Bf[(bk8+3)*68+bm]=b1r.w;
        Bf[(bk8+4)*68+bm]=b2r.x; Bf[(bk8+5)*68+bm]=b2r.y;
        Bf[(bk8+6)*68+bm]=b2r.z; Bf[(bk8+7)*68+bm]=b2r.w;
        __syncthreads();

        if (k0 + 32 < 256) {
            int kn = k0 + 32;
            a0r = *(const float4*)&g_msg[(r0+am )*256 + kn + ak4 ];
            a1r = *(const float4*)&g_msg[(r0+am2)*256 + kn + ak42];
            b1r = *(const float4*)&Wp[(n0+bm)*256 + kn + bk8];
            b2r = *(const float4*)&Wp[(n0+bm)*256 + kn + bk8 + 4];
        }

#pragma unroll
        for (int kk = 0; kk < 32; kk++) {
            float4 a = *(const float4*)&As[kk][ty*4];
            ull ap0 = pack2(a.x), ap1 = pack2(a.y), ap2 = pack2(a.z), ap3 = pack2(a.w);
#pragma unroll
            for (int u = 0; u < 2; u++) {
                ull b = Bs2[kk][tx + 16*u];
                c2[0][u] = fma2(ap0, b, c2[0][u]);
                c2[1][u] = fma2(ap1, b, c2[1][u]);
                c2[2][u] = fma2(ap2, b, c2[2][u]);
                c2[3][u] = fma2(ap3, b, c2[3][u]);
            }
        }
        __syncthreads();
    }
#pragma unroll
    for (int i = 0; i < 4; i++)
#pragma unroll
        for (int u = 0; u < 2; u++) {
            float lo, hi; unpack2(c2[i][u], lo, hi);
            int row = r0 + ty*4 + i;
            int col = n0 + 2*(tx + 16*u);
            int b = row >> 11, l = row & 2047, h = col >> 5, d = col & 31;
            const float* vres = &g_v[(((b<<3)+h)*2048 + l)*32 + d];
            float2 o;
            o.x = lo + bp[col]   + vres[0];
            o.y = hi + bp[col+1] + vres[1];
            *(float2*)&out[row*256 + col] = o;
        }
}

// ---------------------------------------------------------------------------
extern "C" void kernel_launch(void* const* d_in, const int* in_sizes, int n_in,
                              void* d_out, int out_size) {
    const float* points = (const float*)d_in[0];
    const float* gam    = (const float*)d_in[1];
    const float* bet    = (const float*)d_in[2];
    const float* wqkv   = (const float*)d_in[3];
    const float* wproj  = (const float*)d_in[4];
    const float* bproj  = (const float*)d_in[5];
    float* out = (float*)d_out;

    ln_kernel<<<ROWS, 256>>>(points, gam, bet);
    qkv_gemm <<<dim3(6, 64), 256>>>(wqkv);
    attn_kernel<<<1024, 128>>>();
    attn_merge<<<512, 256>>>(out);
    proj_gemm<<<dim3(4, 64), 256>>>(wproj, bproj, out);
}